// round 13
// baseline (speedup 1.0000x reference)
#include <cuda_runtime.h>
#include <math.h>

#define BROWS 2048
#define NCLS  1000
#define KDIM  2048
#define NSTEPS 100

#define LRc   0.1f
#define B1c   0.9f
#define B2c   0.999f
#define EPSc  1e-8f
#define BETAc 5.0f
#define TAUc  6.0f
#define PI_F  3.14159274101257324f   // float(np.pi)

// ---------------- device scratch (static, no allocation) ----------------
__device__ float  g_z[BROWS * NCLS];
__device__ float2 g_mv[BROWS * NCLS];     // interleaved Adam m,v
__device__ float  g_T[BROWS * BROWS];     // l_trg, class-slot layout
__device__ float  g_topz[BROWS];
__device__ float  g_topu2[2][BROWS];      // double-buffered topu (slot order)
__device__ float  g_rowmax[BROWS];
__device__ float  g_sumexp[BROWS];
__device__ int    g_rowarg[BROWS];
__device__ float  g_ptrg[BROWS];
__device__ int    g_y[BROWS];
__device__ int    g_allowed[NCLS];
__device__ unsigned int g_maskw[32];      // allowed bitmask (1000 bits)
__device__ int    g_count[NCLS];
__device__ int    g_start[NCLS];
__device__ int    g_cursor[NCLS];
__device__ int    g_member[BROWS];        // row j, sorted by class
__device__ int    g_classOf[BROWS];       // class of slot k
__device__ int    g_slotOfRow[BROWS];     // inverse of g_member
__device__ int    g_istar;
__device__ int    g_cstar;
__device__ float  g_rmaxstar;
__device__ float  g_sumexpstar;
__device__ float  g_coef;

// ---------------- GEMM: z = x @ W + b ----------------
// 128x64 tile, 8x4 per thread. As stored K-MAJOR (As[kk][m], stride 132) so
// the inner loop reads A as 2x LDS.128 broadcast instead of 8x LDS.32.
// BIT-EXACT vs R9/R11 GEMM: each output element is one fma chain over k
// strictly ascending (k0 outer, kk inner), bias added once at the end.
#define AS_STRIDE 132
__global__ void __launch_bounds__(256)
gemm_kernel(const float* __restrict__ x,
            const float* __restrict__ W,
            const float* __restrict__ bias) {
    __shared__ float As[16][AS_STRIDE];   // [kk][m]
    __shared__ float Bs[16][64];          // [kk][n]
    const int tid = threadIdx.x;
    const int tx = tid & 15;
    const int ty = tid >> 4;
    const int row0 = blockIdx.y * 128;
    const int col0 = blockIdx.x * 64;

    const int bk = tid >> 4;
    const int bn = (tid & 15) * 4;

    float acc[8][4];
#pragma unroll
    for (int i = 0; i < 8; ++i)
#pragma unroll
        for (int j = 0; j < 4; ++j) acc[i][j] = 0.f;

    for (int k0 = 0; k0 < KDIM; k0 += 16) {
#pragma unroll
        for (int q = 0; q < 2; ++q) {
            int idx = tid * 2 + q;            // 0..511
            int m  = idx >> 2;                // 0..127
            int kk = (idx & 3) * 4;           // 0,4,8,12
            float4 xa = *reinterpret_cast<const float4*>(
                &x[(size_t)(row0 + m) * KDIM + k0 + kk]);
            As[kk + 0][m] = xa.x;
            As[kk + 1][m] = xa.y;
            As[kk + 2][m] = xa.z;
            As[kk + 3][m] = xa.w;
        }
        {
            int n = col0 + bn;
            float4 wb;
            if (n + 3 < NCLS) {
                wb = *reinterpret_cast<const float4*>(&W[(size_t)(k0 + bk) * NCLS + n]);
            } else {
                wb = make_float4(0.f, 0.f, 0.f, 0.f);
            }
            *reinterpret_cast<float4*>(&Bs[bk][bn]) = wb;
        }
        __syncthreads();
#pragma unroll
        for (int kk = 0; kk < 16; ++kk) {
            float4 a0 = *reinterpret_cast<const float4*>(&As[kk][ty * 8 + 0]);
            float4 a1 = *reinterpret_cast<const float4*>(&As[kk][ty * 8 + 4]);
            float a[8] = {a0.x, a0.y, a0.z, a0.w, a1.x, a1.y, a1.z, a1.w};
            float4 bb = *reinterpret_cast<const float4*>(&Bs[kk][tx * 4]);
#pragma unroll
            for (int i = 0; i < 8; ++i) {
                acc[i][0] = fmaf(a[i], bb.x, acc[i][0]);
                acc[i][1] = fmaf(a[i], bb.y, acc[i][1]);
                acc[i][2] = fmaf(a[i], bb.z, acc[i][2]);
                acc[i][3] = fmaf(a[i], bb.w, acc[i][3]);
            }
        }
        __syncthreads();
    }
#pragma unroll
    for (int i = 0; i < 8; ++i) {
        int row = row0 + ty * 8 + i;
#pragma unroll
        for (int j = 0; j < 4; ++j) {
            int col = col0 + tx * 4 + j;
            if (col < NCLS) g_z[(size_t)row * NCLS + col] = acc[i][j] + bias[col];
        }
    }
}

// ---------------- setup kernels (identical arithmetic to R1) ----------------
__global__ void init_class_kernel() {
    int c = blockIdx.x * blockDim.x + threadIdx.x;
    if (c < NCLS) { g_allowed[c] = 1; g_count[c] = 0; g_cursor[c] = 0; }
}

__global__ void statsz_kernel() {
    int row = blockIdx.x;
    const float* a = g_z + (size_t)row * NCLS;
    int tid = threadIdx.x;

    float va[4];
    int   nv = 0;
    float vmax = -3.402823466e38f;
    int   vidx = NCLS;
    for (int c = tid; c < NCLS; c += 256) {
        float v = a[c];
        va[nv++] = v;
        if (v > vmax) { vmax = v; vidx = c; }
    }
    __shared__ float smax[256];
    __shared__ int   sidx[256];
    __shared__ float ssum[256];
    smax[tid] = vmax; sidx[tid] = vidx;
    __syncthreads();
    for (int s = 128; s > 0; s >>= 1) {
        if (tid < s) {
            float ov = smax[tid + s]; int oi = sidx[tid + s];
            if (ov > smax[tid] || (ov == smax[tid] && oi < sidx[tid])) { smax[tid] = ov; sidx[tid] = oi; }
        }
        __syncthreads();
    }
    float rmax = smax[0];
    float se = 0.f;
    for (int q = 0; q < nv; ++q) se += expf(va[q] - rmax);
    ssum[tid] = se;
    __syncthreads();
    for (int s = 128; s > 0; s >>= 1) {
        if (tid < s) ssum[tid] += ssum[tid + s];
        __syncthreads();
    }
    if (tid == 0) {
        g_rowmax[row] = rmax;
        g_sumexp[row] = ssum[0];
        g_rowarg[row] = sidx[0];
        g_y[row] = sidx[0];
        g_ptrg[row] = 1.0f / ssum[0];
    }
}

__global__ void mark_kernel() {
    int i = blockIdx.x * blockDim.x + threadIdx.x;
    if (i < BROWS) {
        int c = g_y[i];
        g_allowed[c] = 0;
        atomicAdd(&g_count[c], 1);
    }
}

__global__ void scan_kernel() {
    if (threadIdx.x == 0 && blockIdx.x == 0) {
        int s = 0;
        for (int c = 0; c < NCLS; ++c) { g_start[c] = s; s += g_count[c]; }
    }
}

__global__ void scatter_kernel() {
    int i = blockIdx.x * blockDim.x + threadIdx.x;
    if (i < BROWS) {
        int c = g_y[i];
        int pos = g_start[c] + atomicAdd(&g_cursor[c], 1);
        g_member[pos]    = i;
        g_classOf[pos]   = c;
        g_slotOfRow[i]   = pos;
    }
}

__global__ void maskw_kernel() {
    int w = threadIdx.x;   // 32 threads
    unsigned int m = 0;
    for (int b = 0; b < 32; ++b) {
        int c = w * 32 + b;
        if (c < NCLS && g_allowed[c]) m |= (1u << b);
    }
    g_maskw[w] = m;
}

// masked top over z + fill initial topu buffer 0 (slot order)
__global__ void topz_kernel() {
    int row = blockIdx.x;
    int tid = threadIdx.x;
    float tmax = -1000.0f;
    for (int c = tid; c < NCLS; c += 256) {
        if (g_allowed[c]) {
            float v = g_z[(size_t)row * NCLS + c];
            if (v > tmax) tmax = v;
        }
    }
    __shared__ float st[256];
    st[tid] = tmax;
    __syncthreads();
    for (int s = 128; s > 0; s >>= 1) {
        if (tid < s) { float o = st[tid + s]; if (o > st[tid]) st[tid] = o; }
        __syncthreads();
    }
    if (tid == 0) {
        g_topz[row] = st[0];
        g_topu2[0][g_slotOfRow[row]] = st[0];
    }
}

__global__ void computeT_kernel() {
    int idx = blockIdx.x * blockDim.x + threadIdx.x;
    int i = idx >> 11;
    int k = idx & 2047;
    int c = g_classOf[k];
    int j = g_member[k];
    float lorg = g_z[(size_t)i * NCLS + c] - g_topz[j];
    float latr = (floorf(lorg / TAUc) + 0.5f) * TAUc;
    float arg  = PI_F * (1.0f - 2.0f * (lorg - latr) / TAUc);
    g_T[idx] = lorg - TAUc * sinf(arg);
}

__global__ void init_u_kernel(float* __restrict__ u) {
    int idx = blockIdx.x * blockDim.x + threadIdx.x;
    u[idx]    = g_z[idx];
    g_mv[idx] = make_float2(0.f, 0.f);
}

// ---------------- global reduce (exact ops -> order-independent, any shape) ----
__global__ void reduce_kernel() {
    __shared__ float sv[1024];
    __shared__ int   si[1024];
    __shared__ float ss[1024];
    const int tid = threadIdx.x;
    float best = 3.402823466e38f;
    int   bi   = 1 << 30;
    for (int j = tid; j < BROWS; j += 1024) {
        float o = __ldcg(&g_sumexp[j]);
        if (o < best || (o == best && j < bi)) { best = o; bi = j; }
    }
    sv[tid] = best; si[tid] = bi;
    __syncthreads();
    for (int s = 512; s > 0; s >>= 1) {
        if (tid < s) {
            float ov = sv[tid + s]; int oi = si[tid + s];
            if (ov < sv[tid] || (ov == sv[tid] && oi < si[tid])) { sv[tid] = ov; si[tid] = oi; }
        }
        __syncthreads();
    }
    int istar = si[0];
    float pmax = 1.0f / sv[0];
    float s1 = 0.f;
    for (int j = tid; j < BROWS; j += 1024) {
        float d = pmax - g_ptrg[j];
        s1 += (d > 0.f) ? 1.f : ((d < 0.f) ? -1.f : 0.f);
    }
    ss[tid] = s1;
    __syncthreads();
    for (int s = 512; s > 0; s >>= 1) {
        if (tid < s) ss[tid] += ss[tid + s];
        __syncthreads();
    }
    if (tid == 0) {
        g_istar      = istar;
        g_cstar      = __ldcg(&g_rowarg[istar]);
        g_rmaxstar   = __ldcg(&g_rowmax[istar]);
        g_sumexpstar = __ldcg(&g_sumexp[istar]);
        g_coef       = BETAc * 2048.0f * ss[0] * pmax;
    }
}

// ---------------- fused per-step kernel (UNCHANGED from R11/R12) ----------------
__global__ void __launch_bounds__(256, 6)
fused_kernel(float* __restrict__ u, int parity, float bc1, float bc2) {
    __shared__ float2 s_pair[BROWS];     // {topu[k], T[k]}
    __shared__ float smax[256];
    __shared__ int   sidx[256];
    __shared__ float stp[256];
    __shared__ float ssum[256];
    __shared__ unsigned int s_mask[32];

    const int i    = blockIdx.x;
    const int tid  = threadIdx.x;
    const int lane = tid & 31;
    const int warp = tid >> 5;
    const float* __restrict__ topuIn = g_topu2[parity];
    float* __restrict__ topuOut      = g_topu2[parity ^ 1];

    {   // stage paired {topu, T} (float4 loads, float2 interleaved stores)
        const float4* T4  = reinterpret_cast<const float4*>(g_T + ((size_t)i << 11));
        const float4* tu4 = reinterpret_cast<const float4*>(topuIn);
        float4 t0 = T4[tid];
        float4 u0 = tu4[tid];
        float4 t1 = T4[tid + 256];
        float4 u1 = tu4[tid + 256];
        int k0 = tid * 4;
        s_pair[k0 + 0] = make_float2(u0.x, t0.x);
        s_pair[k0 + 1] = make_float2(u0.y, t0.y);
        s_pair[k0 + 2] = make_float2(u0.z, t0.z);
        s_pair[k0 + 3] = make_float2(u0.w, t0.w);
        int k1 = (tid + 256) * 4;
        s_pair[k1 + 0] = make_float2(u1.x, t1.x);
        s_pair[k1 + 1] = make_float2(u1.y, t1.y);
        s_pair[k1 + 2] = make_float2(u1.z, t1.z);
        s_pair[k1 + 3] = make_float2(u1.w, t1.w);
        if (tid < 32) s_mask[tid] = g_maskw[tid];
    }
    const int   istar      = g_istar;      // written by previous reduce launch
    const int   cstar      = g_cstar;
    const float rmaxstar   = g_rmaxstar;
    const float sumexpstar = g_sumexpstar;
    const float coef       = g_coef;

    // hoist u + mv loads for all 4 column chunks (MLP)
    float  uv4[4];
    float2 mv4[4];
    int    cls_s[4], cls_e[4];
#pragma unroll
    for (int q = 0; q < 4; ++q) {
        int c = tid + q * 256;
        if (c < NCLS) {
            int idx = i * NCLS + c;
            uv4[q] = u[idx];
            mv4[q] = g_mv[idx];
            cls_s[q] = g_start[c];
            cls_e[q] = cls_s[q] + g_count[c];
        } else { uv4[q] = 0.f; mv4[q] = make_float2(0.f, 0.f); cls_s[q] = 0; cls_e[q] = 0; }
    }
    __syncthreads();

    // ---- gradient + Adam + u update; keep new u in va[] (R1 stats order) ----
    float va[4];
    int   nv = 0;
    float vmax = -3.402823466e38f;
    int   vidx = NCLS;
    float tmax = -1000.0f;
#pragma unroll
    for (int q = 0; q < 4; ++q) {
        int c = tid + q * 256;
        if (c < NCLS) {
            int idx = i * NCLS + c;
            float uv = uv4[q];
            float g = 0.f;
            for (int k = cls_s[q]; k < cls_e[q]; ++k) {
                float2 p = s_pair[k];
                float d = uv - p.x - p.y;
                g += (d > 0.f) ? 1.f : ((d < 0.f) ? -1.f : 0.f);
            }
            if (i == istar) {
                float p = expf(uv - rmaxstar) / sumexpstar;
                float ind = (c == cstar) ? 1.f : 0.f;
                g += coef * (ind - p);
            }
            float mv = B1c * mv4[q].x + (1.0f - B1c) * g;
            float vv = B2c * mv4[q].y + (1.0f - B2c) * g * g;
            g_mv[idx] = make_float2(mv, vv);
            float mhat = mv / bc1;
            float vhat = vv / bc2;
            float nu = uv - LRc * mhat / (sqrtf(vhat) + EPSc);
            u[idx] = nu;
            va[nv++] = nu;
            if (nu > vmax) { vmax = nu; vidx = c; }
            if ((s_mask[c >> 5] >> (c & 31)) & 1u) { if (nu > tmax) tmax = nu; }
        }
    }

    // ---- max/argmax/topu: EXACT ops -> warp-shuffle-first (order-free) ----
#pragma unroll
    for (int off = 16; off > 0; off >>= 1) {
        float ov = __shfl_down_sync(0xffffffffu, vmax, off);
        int   oi = __shfl_down_sync(0xffffffffu, vidx, off);
        float ot = __shfl_down_sync(0xffffffffu, tmax, off);
        if (ov > vmax || (ov == vmax && oi < vidx)) { vmax = ov; vidx = oi; }
        if (ot > tmax) tmax = ot;
    }
    if (lane == 0) { smax[warp] = vmax; sidx[warp] = vidx; stp[warp] = tmax; }
    __syncthreads();
    if (tid < 8) {
        float mv_ = smax[tid]; int mi_ = sidx[tid]; float tp_ = stp[tid];
        __syncwarp(0x000000ffu);
#pragma unroll
        for (int off = 4; off > 0; off >>= 1) {
            float ov = __shfl_down_sync(0x000000ffu, mv_, off);
            int   oi = __shfl_down_sync(0x000000ffu, mi_, off);
            float ot = __shfl_down_sync(0x000000ffu, tp_, off);
            if (ov > mv_ || (ov == mv_ && oi < mi_)) { mv_ = ov; mi_ = oi; }
            if (ot > tp_) tp_ = ot;
        }
        if (tid == 0) { smax[0] = mv_; sidx[0] = mi_; stp[0] = tp_; }
    }
    __syncthreads();
    const float rmax  = smax[0];
    const int   argr  = sidx[0];
    const float tmaxr = stp[0];

    // ---- sumexp: R1's exact tree pairing (rounding-sensitive, unchanged) ----
    float se = 0.f;
    for (int q = 0; q < nv; ++q) se += expf(va[q] - rmax);
    ssum[tid] = se;
    __syncthreads();
#pragma unroll
    for (int s = 128; s >= 32; s >>= 1) {
        if (tid < s) ssum[tid] += ssum[tid + s];
        __syncthreads();
    }
    if (tid < 32) {
        float sum_ = ssum[tid];
        __syncwarp(0xffffffffu);
#pragma unroll
        for (int off = 16; off > 0; off >>= 1)
            sum_ += __shfl_down_sync(0xffffffffu, sum_, off);
        if (tid == 0) {
            g_rowmax[i] = rmax;
            g_sumexp[i] = sum_;
            g_rowarg[i] = argr;
            topuOut[g_slotOfRow[i]] = tmaxr;
        }
    }
}

// ---------------- launch ----------------
extern "C" void kernel_launch(void* const* d_in, const int* in_sizes, int n_in,
                              void* d_out, int out_size) {
    const float* x = nullptr; const float* W = nullptr; const float* b = nullptr;
    for (int i = 0; i < n_in; ++i) {
        if (in_sizes[i] == BROWS * KDIM)      x = (const float*)d_in[i];
        else if (in_sizes[i] == KDIM * NCLS)  W = (const float*)d_in[i];
        else if (in_sizes[i] == NCLS)         b = (const float*)d_in[i];
    }
    float* u = (float*)d_out;

    // Idx 0-2: idempotent init (run 3x so gemm lands at our idx 3 = global
    // launch #5, which the fixed ncu capture (-s 5 -c 1) profiles).
    init_class_kernel<<<4, 256>>>();                   // idx 0
    init_class_kernel<<<4, 256>>>();                   // idx 1
    init_class_kernel<<<4, 256>>>();                   // idx 2

    dim3 gemm_grid((NCLS + 63) / 64, BROWS / 128);
    gemm_kernel<<<gemm_grid, 256>>>(x, W, b);          // idx 3  <-- PROFILED

    statsz_kernel<<<BROWS, 256>>>();
    mark_kernel<<<8, 256>>>();
    scan_kernel<<<1, 1>>>();
    scatter_kernel<<<8, 256>>>();
    maskw_kernel<<<1, 32>>>();
    topz_kernel<<<BROWS, 256>>>();
    computeT_kernel<<<(BROWS * BROWS) / 256, 256>>>();
    init_u_kernel<<<(BROWS * NCLS) / 256, 256>>>(u);
    reduce_kernel<<<1, 1024>>>();

    for (int t = 1; t <= NSTEPS; ++t) {
        float bc1 = (float)(1.0 - pow((double)B1c, (double)t));
        float bc2 = (float)(1.0 - pow((double)B2c, (double)t));
        fused_kernel<<<BROWS, 256>>>(u, (t - 1) & 1, bc1, bc2);
        reduce_kernel<<<1, 1024>>>();
    }
}

// round 14
// speedup vs baseline: 1.0518x; 1.0518x over previous
#include <cuda_runtime.h>
#include <math.h>

#define BROWS 2048
#define NCLS  1000
#define KDIM  2048
#define NSTEPS 100

#define LRc   0.1f
#define B1c   0.9f
#define B2c   0.999f
#define EPSc  1e-8f
#define BETAc 5.0f
#define TAUc  6.0f
#define PI_F  3.14159274101257324f   // float(np.pi)

// ---------------- device scratch (static, no allocation) ----------------
__device__ float  g_z[BROWS * NCLS];
__device__ float2 g_mv[BROWS * NCLS];     // interleaved Adam m,v
__device__ float  g_T[BROWS * BROWS];     // l_trg, class-slot layout
__device__ float  g_topz[BROWS];
__device__ float  g_topu2[2][BROWS];      // double-buffered topu (slot order)
__device__ float  g_rowmax[BROWS];
__device__ float  g_sumexp[BROWS];
__device__ int    g_rowarg[BROWS];
__device__ float  g_ptrg[BROWS];
__device__ int    g_y[BROWS];
__device__ int    g_allowed[NCLS];
__device__ unsigned int g_maskw[32];      // allowed bitmask (1000 bits)
__device__ int    g_count[NCLS];
__device__ int    g_start[NCLS];
__device__ int    g_cursor[NCLS];
__device__ int    g_member[BROWS];        // row j, sorted by class
__device__ int    g_classOf[BROWS];       // class of slot k
__device__ int    g_slotOfRow[BROWS];     // inverse of g_member
__device__ int    g_istar;
__device__ int    g_cstar;
__device__ float  g_rmaxstar;
__device__ float  g_sumexpstar;
__device__ float  g_coef;

// ---------------- GEMM: z = x @ W + b (m-major As — best measured, 256us) ----
__global__ void __launch_bounds__(256)
gemm_kernel(const float* __restrict__ x,
            const float* __restrict__ W,
            const float* __restrict__ bias) {
    __shared__ float As[128][16];
    __shared__ float Bs[16][64];
    const int tid = threadIdx.x;
    const int tx = tid & 15;
    const int ty = tid >> 4;
    const int row0 = blockIdx.y * 128;
    const int col0 = blockIdx.x * 64;

    const int bk = tid >> 4;
    const int bn = (tid & 15) * 4;

    float acc[8][4];
#pragma unroll
    for (int i = 0; i < 8; ++i)
#pragma unroll
        for (int j = 0; j < 4; ++j) acc[i][j] = 0.f;

    for (int k0 = 0; k0 < KDIM; k0 += 16) {
#pragma unroll
        for (int q = 0; q < 2; ++q) {
            int idx = tid * 2 + q;
            int m  = idx >> 2;
            int kk = (idx & 3) * 4;
            float4 xa = *reinterpret_cast<const float4*>(
                &x[(size_t)(row0 + m) * KDIM + k0 + kk]);
            *reinterpret_cast<float4*>(&As[m][kk]) = xa;
        }
        {
            int n = col0 + bn;
            float4 wb;
            if (n + 3 < NCLS) {
                wb = *reinterpret_cast<const float4*>(&W[(size_t)(k0 + bk) * NCLS + n]);
            } else {
                wb = make_float4(0.f, 0.f, 0.f, 0.f);
            }
            *reinterpret_cast<float4*>(&Bs[bk][bn]) = wb;
        }
        __syncthreads();
#pragma unroll
        for (int kk = 0; kk < 16; ++kk) {
            float a[8];
#pragma unroll
            for (int i = 0; i < 8; ++i) a[i] = As[ty * 8 + i][kk];
            float4 bb = *reinterpret_cast<const float4*>(&Bs[kk][tx * 4]);
#pragma unroll
            for (int i = 0; i < 8; ++i) {
                acc[i][0] = fmaf(a[i], bb.x, acc[i][0]);
                acc[i][1] = fmaf(a[i], bb.y, acc[i][1]);
                acc[i][2] = fmaf(a[i], bb.z, acc[i][2]);
                acc[i][3] = fmaf(a[i], bb.w, acc[i][3]);
            }
        }
        __syncthreads();
    }
#pragma unroll
    for (int i = 0; i < 8; ++i) {
        int row = row0 + ty * 8 + i;
#pragma unroll
        for (int j = 0; j < 4; ++j) {
            int col = col0 + tx * 4 + j;
            if (col < NCLS) g_z[(size_t)row * NCLS + col] = acc[i][j] + bias[col];
        }
    }
}

// ---------------- setup kernels (identical arithmetic to R1) ----------------
__global__ void init_class_kernel() {
    int c = blockIdx.x * blockDim.x + threadIdx.x;
    if (c < NCLS) { g_allowed[c] = 1; g_count[c] = 0; g_cursor[c] = 0; }
}

__global__ void statsz_kernel() {
    int row = blockIdx.x;
    const float* a = g_z + (size_t)row * NCLS;
    int tid = threadIdx.x;

    float va[4];
    int   nv = 0;
    float vmax = -3.402823466e38f;
    int   vidx = NCLS;
    for (int c = tid; c < NCLS; c += 256) {
        float v = a[c];
        va[nv++] = v;
        if (v > vmax) { vmax = v; vidx = c; }
    }
    __shared__ float smax[256];
    __shared__ int   sidx[256];
    __shared__ float ssum[256];
    smax[tid] = vmax; sidx[tid] = vidx;
    __syncthreads();
    for (int s = 128; s > 0; s >>= 1) {
        if (tid < s) {
            float ov = smax[tid + s]; int oi = sidx[tid + s];
            if (ov > smax[tid] || (ov == smax[tid] && oi < sidx[tid])) { smax[tid] = ov; sidx[tid] = oi; }
        }
        __syncthreads();
    }
    float rmax = smax[0];
    float se = 0.f;
    for (int q = 0; q < nv; ++q) se += expf(va[q] - rmax);
    ssum[tid] = se;
    __syncthreads();
    for (int s = 128; s > 0; s >>= 1) {
        if (tid < s) ssum[tid] += ssum[tid + s];
        __syncthreads();
    }
    if (tid == 0) {
        g_rowmax[row] = rmax;
        g_sumexp[row] = ssum[0];
        g_rowarg[row] = sidx[0];
        g_y[row] = sidx[0];
        g_ptrg[row] = 1.0f / ssum[0];
    }
}

__global__ void mark_kernel() {
    int i = blockIdx.x * blockDim.x + threadIdx.x;
    if (i < BROWS) {
        int c = g_y[i];
        g_allowed[c] = 0;
        atomicAdd(&g_count[c], 1);
    }
}

__global__ void scan_kernel() {
    if (threadIdx.x == 0 && blockIdx.x == 0) {
        int s = 0;
        for (int c = 0; c < NCLS; ++c) { g_start[c] = s; s += g_count[c]; }
    }
}

__global__ void scatter_kernel() {
    int i = blockIdx.x * blockDim.x + threadIdx.x;
    if (i < BROWS) {
        int c = g_y[i];
        int pos = g_start[c] + atomicAdd(&g_cursor[c], 1);
        g_member[pos]    = i;
        g_classOf[pos]   = c;
        g_slotOfRow[i]   = pos;
    }
}

__global__ void maskw_kernel() {
    int w = threadIdx.x;   // 32 threads
    unsigned int m = 0;
    for (int b = 0; b < 32; ++b) {
        int c = w * 32 + b;
        if (c < NCLS && g_allowed[c]) m |= (1u << b);
    }
    g_maskw[w] = m;
}

// masked top over z + fill initial topu buffer 0 (slot order)
__global__ void topz_kernel() {
    int row = blockIdx.x;
    int tid = threadIdx.x;
    float tmax = -1000.0f;
    for (int c = tid; c < NCLS; c += 256) {
        if (g_allowed[c]) {
            float v = g_z[(size_t)row * NCLS + c];
            if (v > tmax) tmax = v;
        }
    }
    __shared__ float st[256];
    st[tid] = tmax;
    __syncthreads();
    for (int s = 128; s > 0; s >>= 1) {
        if (tid < s) { float o = st[tid + s]; if (o > st[tid]) st[tid] = o; }
        __syncthreads();
    }
    if (tid == 0) {
        g_topz[row] = st[0];
        g_topu2[0][g_slotOfRow[row]] = st[0];
    }
}

// T[i][k] = l_trg, one block per row i. z-row staged in smem (coalesced);
// g_topz[g_member[k]] replaced by g_topu2[0][k] — the SAME stored float
// (topz_kernel writes st[0] to both g_topz[row] and g_topu2[0][slotOfRow[row]],
// and slotOfRow[member[k]] == k). Per-element formula unchanged -> bit-exact.
__global__ void __launch_bounds__(256)
computeT_kernel() {
    __shared__ float s_z[NCLS];
    const int i   = blockIdx.x;
    const int tid = threadIdx.x;
    for (int c = tid; c < NCLS; c += 256)
        s_z[c] = g_z[(size_t)i * NCLS + c];
    __syncthreads();
    const size_t base = (size_t)i << 11;
#pragma unroll
    for (int q = 0; q < 8; ++q) {
        int k = tid + q * 256;
        int c = g_classOf[k];
        float tz = g_topu2[0][k];
        float lorg = s_z[c] - tz;
        float latr = (floorf(lorg / TAUc) + 0.5f) * TAUc;
        float arg  = PI_F * (1.0f - 2.0f * (lorg - latr) / TAUc);
        g_T[base + k] = lorg - TAUc * sinf(arg);
    }
}

__global__ void init_u_kernel(float* __restrict__ u) {
    int idx = blockIdx.x * blockDim.x + threadIdx.x;
    u[idx]    = g_z[idx];
    g_mv[idx] = make_float2(0.f, 0.f);
}

// ---------------- global reduce (exact ops -> order-independent, any shape) ----
__global__ void reduce_kernel() {
    __shared__ float sv[1024];
    __shared__ int   si[1024];
    __shared__ float ss[1024];
    const int tid = threadIdx.x;
    float best = 3.402823466e38f;
    int   bi   = 1 << 30;
    for (int j = tid; j < BROWS; j += 1024) {
        float o = __ldcg(&g_sumexp[j]);
        if (o < best || (o == best && j < bi)) { best = o; bi = j; }
    }
    sv[tid] = best; si[tid] = bi;
    __syncthreads();
    for (int s = 512; s > 0; s >>= 1) {
        if (tid < s) {
            float ov = sv[tid + s]; int oi = si[tid + s];
            if (ov < sv[tid] || (ov == sv[tid] && oi < si[tid])) { sv[tid] = ov; si[tid] = oi; }
        }
        __syncthreads();
    }
    int istar = si[0];
    float pmax = 1.0f / sv[0];
    float s1 = 0.f;
    for (int j = tid; j < BROWS; j += 1024) {
        float d = pmax - g_ptrg[j];
        s1 += (d > 0.f) ? 1.f : ((d < 0.f) ? -1.f : 0.f);
    }
    ss[tid] = s1;
    __syncthreads();
    for (int s = 512; s > 0; s >>= 1) {
        if (tid < s) ss[tid] += ss[tid + s];
        __syncthreads();
    }
    if (tid == 0) {
        g_istar      = istar;
        g_cstar      = __ldcg(&g_rowarg[istar]);
        g_rmaxstar   = __ldcg(&g_rowmax[istar]);
        g_sumexpstar = __ldcg(&g_sumexp[istar]);
        g_coef       = BETAc * 2048.0f * ss[0] * pmax;
    }
}

// ---------------- fused per-step kernel (UNCHANGED from R11) ----------------
__global__ void __launch_bounds__(256, 6)
fused_kernel(float* __restrict__ u, int parity, float bc1, float bc2) {
    __shared__ float2 s_pair[BROWS];     // {topu[k], T[k]}
    __shared__ float smax[256];
    __shared__ int   sidx[256];
    __shared__ float stp[256];
    __shared__ float ssum[256];
    __shared__ unsigned int s_mask[32];

    const int i    = blockIdx.x;
    const int tid  = threadIdx.x;
    const int lane = tid & 31;
    const int warp = tid >> 5;
    const float* __restrict__ topuIn = g_topu2[parity];
    float* __restrict__ topuOut      = g_topu2[parity ^ 1];

    {   // stage paired {topu, T} (float4 loads, float2 interleaved stores)
        const float4* T4  = reinterpret_cast<const float4*>(g_T + ((size_t)i << 11));
        const float4* tu4 = reinterpret_cast<const float4*>(topuIn);
        float4 t0 = T4[tid];
        float4 u0 = tu4[tid];
        float4 t1 = T4[tid + 256];
        float4 u1 = tu4[tid + 256];
        int k0 = tid * 4;
        s_pair[k0 + 0] = make_float2(u0.x, t0.x);
        s_pair[k0 + 1] = make_float2(u0.y, t0.y);
        s_pair[k0 + 2] = make_float2(u0.z, t0.z);
        s_pair[k0 + 3] = make_float2(u0.w, t0.w);
        int k1 = (tid + 256) * 4;
        s_pair[k1 + 0] = make_float2(u1.x, t1.x);
        s_pair[k1 + 1] = make_float2(u1.y, t1.y);
        s_pair[k1 + 2] = make_float2(u1.z, t1.z);
        s_pair[k1 + 3] = make_float2(u1.w, t1.w);
        if (tid < 32) s_mask[tid] = g_maskw[tid];
    }
    const int   istar      = g_istar;      // written by previous reduce launch
    const int   cstar      = g_cstar;
    const float rmaxstar   = g_rmaxstar;
    const float sumexpstar = g_sumexpstar;
    const float coef       = g_coef;

    // hoist u + mv loads for all 4 column chunks (MLP)
    float  uv4[4];
    float2 mv4[4];
    int    cls_s[4], cls_e[4];
#pragma unroll
    for (int q = 0; q < 4; ++q) {
        int c = tid + q * 256;
        if (c < NCLS) {
            int idx = i * NCLS + c;
            uv4[q] = u[idx];
            mv4[q] = g_mv[idx];
            cls_s[q] = g_start[c];
            cls_e[q] = cls_s[q] + g_count[c];
        } else { uv4[q] = 0.f; mv4[q] = make_float2(0.f, 0.f); cls_s[q] = 0; cls_e[q] = 0; }
    }
    __syncthreads();

    // ---- gradient + Adam + u update; keep new u in va[] (R1 stats order) ----
    float va[4];
    int   nv = 0;
    float vmax = -3.402823466e38f;
    int   vidx = NCLS;
    float tmax = -1000.0f;
#pragma unroll
    for (int q = 0; q < 4; ++q) {
        int c = tid + q * 256;
        if (c < NCLS) {
            int idx = i * NCLS + c;
            float uv = uv4[q];
            float g = 0.f;
            for (int k = cls_s[q]; k < cls_e[q]; ++k) {
                float2 p = s_pair[k];
                float d = uv - p.x - p.y;
                g += (d > 0.f) ? 1.f : ((d < 0.f) ? -1.f : 0.f);
            }
            if (i == istar) {
                float p = expf(uv - rmaxstar) / sumexpstar;
                float ind = (c == cstar) ? 1.f : 0.f;
                g += coef * (ind - p);
            }
            float mv = B1c * mv4[q].x + (1.0f - B1c) * g;
            float vv = B2c * mv4[q].y + (1.0f - B2c) * g * g;
            g_mv[idx] = make_float2(mv, vv);
            float mhat = mv / bc1;
            float vhat = vv / bc2;
            float nu = uv - LRc * mhat / (sqrtf(vhat) + EPSc);
            u[idx] = nu;
            va[nv++] = nu;
            if (nu > vmax) { vmax = nu; vidx = c; }
            if ((s_mask[c >> 5] >> (c & 31)) & 1u) { if (nu > tmax) tmax = nu; }
        }
    }

    // ---- max/argmax/topu: EXACT ops -> warp-shuffle-first (order-free) ----
#pragma unroll
    for (int off = 16; off > 0; off >>= 1) {
        float ov = __shfl_down_sync(0xffffffffu, vmax, off);
        int   oi = __shfl_down_sync(0xffffffffu, vidx, off);
        float ot = __shfl_down_sync(0xffffffffu, tmax, off);
        if (ov > vmax || (ov == vmax && oi < vidx)) { vmax = ov; vidx = oi; }
        if (ot > tmax) tmax = ot;
    }
    if (lane == 0) { smax[warp] = vmax; sidx[warp] = vidx; stp[warp] = tmax; }
    __syncthreads();
    if (tid < 8) {
        float mv_ = smax[tid]; int mi_ = sidx[tid]; float tp_ = stp[tid];
        __syncwarp(0x000000ffu);
#pragma unroll
        for (int off = 4; off > 0; off >>= 1) {
            float ov = __shfl_down_sync(0x000000ffu, mv_, off);
            int   oi = __shfl_down_sync(0x000000ffu, mi_, off);
            float ot = __shfl_down_sync(0x000000ffu, tp_, off);
            if (ov > mv_ || (ov == mv_ && oi < mi_)) { mv_ = ov; mi_ = oi; }
            if (ot > tp_) tp_ = ot;
        }
        if (tid == 0) { smax[0] = mv_; sidx[0] = mi_; stp[0] = tp_; }
    }
    __syncthreads();
    const float rmax  = smax[0];
    const int   argr  = sidx[0];
    const float tmaxr = stp[0];

    // ---- sumexp: R1's exact tree pairing (rounding-sensitive, unchanged) ----
    float se = 0.f;
    for (int q = 0; q < nv; ++q) se += expf(va[q] - rmax);
    ssum[tid] = se;
    __syncthreads();
#pragma unroll
    for (int s = 128; s >= 32; s >>= 1) {
        if (tid < s) ssum[tid] += ssum[tid + s];
        __syncthreads();
    }
    if (tid < 32) {
        float sum_ = ssum[tid];
        __syncwarp(0xffffffffu);
#pragma unroll
        for (int off = 16; off > 0; off >>= 1)
            sum_ += __shfl_down_sync(0xffffffffu, sum_, off);
        if (tid == 0) {
            g_rowmax[i] = rmax;
            g_sumexp[i] = sum_;
            g_rowarg[i] = argr;
            topuOut[g_slotOfRow[i]] = tmaxr;
        }
    }
}

// ---------------- launch ----------------
extern "C" void kernel_launch(void* const* d_in, const int* in_sizes, int n_in,
                              void* d_out, int out_size) {
    const float* x = nullptr; const float* W = nullptr; const float* b = nullptr;
    for (int i = 0; i < n_in; ++i) {
        if (in_sizes[i] == BROWS * KDIM)      x = (const float*)d_in[i];
        else if (in_sizes[i] == KDIM * NCLS)  W = (const float*)d_in[i];
        else if (in_sizes[i] == NCLS)         b = (const float*)d_in[i];
    }
    float* u = (float*)d_out;

    dim3 gemm_grid((NCLS + 63) / 64, BROWS / 128);
    gemm_kernel<<<gemm_grid, 256>>>(x, W, b);

    init_class_kernel<<<4, 256>>>();
    statsz_kernel<<<BROWS, 256>>>();
    mark_kernel<<<8, 256>>>();
    scan_kernel<<<1, 1>>>();
    scatter_kernel<<<8, 256>>>();
    maskw_kernel<<<1, 32>>>();
    topz_kernel<<<BROWS, 256>>>();
    computeT_kernel<<<BROWS, 256>>>();
    init_u_kernel<<<(BROWS * NCLS) / 256, 256>>>(u);
    reduce_kernel<<<1, 1024>>>();

    for (int t = 1; t <= NSTEPS; ++t) {
        float bc1 = (float)(1.0 - pow((double)B1c, (double)t));
        float bc2 = (float)(1.0 - pow((double)B2c, (double)t));
        fused_kernel<<<BROWS, 256>>>(u, (t - 1) & 1, bc1, bc2);
        reduce_kernel<<<1, 1024>>>();
    }
}

// round 16
// speedup vs baseline: 1.0655x; 1.0131x over previous
#include <cuda_runtime.h>
#include <math.h>

#define BROWS 2048
#define NCLS  1000
#define KDIM  2048
#define NSTEPS 100

#define LRc   0.1f
#define B1c   0.9f
#define B2c   0.999f
#define EPSc  1e-8f
#define BETAc 5.0f
#define TAUc  6.0f
#define PI_F  3.14159274101257324f   // float(np.pi)

// ---------------- device scratch (static, no allocation) ----------------
__device__ float  g_z[BROWS * NCLS];
__device__ float2 g_mv[BROWS * NCLS];     // interleaved Adam m,v
__device__ float  g_T[BROWS * BROWS];     // l_trg, class-slot layout
__device__ float  g_topz[BROWS];
__device__ float  g_topu2[2][BROWS];      // double-buffered topu (slot order)
__device__ float  g_rowmax[BROWS];
__device__ float  g_sumexp[BROWS];
__device__ int    g_rowarg[BROWS];
__device__ float  g_ptrg[BROWS];
__device__ int    g_y[BROWS];
__device__ int    g_allowed[NCLS];
__device__ unsigned int g_maskw[32];      // allowed bitmask (1000 bits)
__device__ int    g_count[NCLS];
__device__ int    g_start[NCLS + 1];      // +1 sentinel: g_start[NCLS] = BROWS
__device__ int    g_cursor[NCLS];
__device__ int    g_member[BROWS];        // row j, sorted by class
__device__ int    g_classOf[BROWS];       // class of slot k
__device__ int    g_slotOfRow[BROWS];     // inverse of g_member
__device__ int    g_istar;
__device__ int    g_cstar;
__device__ float  g_rmaxstar;
__device__ float  g_sumexpstar;
__device__ float  g_coef;

// ---------------- GEMM: z = x @ W + b (at FFMA ceiling — do not touch) ----------
__global__ void __launch_bounds__(256)
gemm_kernel(const float* __restrict__ x,
            const float* __restrict__ W,
            const float* __restrict__ bias) {
    __shared__ float As[128][16];
    __shared__ float Bs[16][64];
    const int tid = threadIdx.x;
    const int tx = tid & 15;
    const int ty = tid >> 4;
    const int row0 = blockIdx.y * 128;
    const int col0 = blockIdx.x * 64;

    const int bk = tid >> 4;
    const int bn = (tid & 15) * 4;

    float acc[8][4];
#pragma unroll
    for (int i = 0; i < 8; ++i)
#pragma unroll
        for (int j = 0; j < 4; ++j) acc[i][j] = 0.f;

    for (int k0 = 0; k0 < KDIM; k0 += 16) {
#pragma unroll
        for (int q = 0; q < 2; ++q) {
            int idx = tid * 2 + q;
            int m  = idx >> 2;
            int kk = (idx & 3) * 4;
            float4 xa = *reinterpret_cast<const float4*>(
                &x[(size_t)(row0 + m) * KDIM + k0 + kk]);
            *reinterpret_cast<float4*>(&As[m][kk]) = xa;
        }
        {
            int n = col0 + bn;
            float4 wb;
            if (n + 3 < NCLS) {
                wb = *reinterpret_cast<const float4*>(&W[(size_t)(k0 + bk) * NCLS + n]);
            } else {
                wb = make_float4(0.f, 0.f, 0.f, 0.f);
            }
            *reinterpret_cast<float4*>(&Bs[bk][bn]) = wb;
        }
        __syncthreads();
#pragma unroll
        for (int kk = 0; kk < 16; ++kk) {
            float a[8];
#pragma unroll
            for (int i = 0; i < 8; ++i) a[i] = As[ty * 8 + i][kk];
            float4 bb = *reinterpret_cast<const float4*>(&Bs[kk][tx * 4]);
#pragma unroll
            for (int i = 0; i < 8; ++i) {
                acc[i][0] = fmaf(a[i], bb.x, acc[i][0]);
                acc[i][1] = fmaf(a[i], bb.y, acc[i][1]);
                acc[i][2] = fmaf(a[i], bb.z, acc[i][2]);
                acc[i][3] = fmaf(a[i], bb.w, acc[i][3]);
            }
        }
        __syncthreads();
    }
#pragma unroll
    for (int i = 0; i < 8; ++i) {
        int row = row0 + ty * 8 + i;
#pragma unroll
        for (int j = 0; j < 4; ++j) {
            int col = col0 + tx * 4 + j;
            if (col < NCLS) g_z[(size_t)row * NCLS + col] = acc[i][j] + bias[col];
        }
    }
}

// ---------------- setup kernels (identical arithmetic to R1) ----------------
__global__ void init_class_kernel() {
    int c = blockIdx.x * blockDim.x + threadIdx.x;
    if (c < NCLS) { g_allowed[c] = 1; g_count[c] = 0; g_cursor[c] = 0; }
}

__global__ void statsz_kernel() {
    int row = blockIdx.x;
    const float* a = g_z + (size_t)row * NCLS;
    int tid = threadIdx.x;

    float va[4];
    int   nv = 0;
    float vmax = -3.402823466e38f;
    int   vidx = NCLS;
    for (int c = tid; c < NCLS; c += 256) {
        float v = a[c];
        va[nv++] = v;
        if (v > vmax) { vmax = v; vidx = c; }
    }
    __shared__ float smax[256];
    __shared__ int   sidx[256];
    __shared__ float ssum[256];
    smax[tid] = vmax; sidx[tid] = vidx;
    __syncthreads();
    for (int s = 128; s > 0; s >>= 1) {
        if (tid < s) {
            float ov = smax[tid + s]; int oi = sidx[tid + s];
            if (ov > smax[tid] || (ov == smax[tid] && oi < sidx[tid])) { smax[tid] = ov; sidx[tid] = oi; }
        }
        __syncthreads();
    }
    float rmax = smax[0];
    float se = 0.f;
    for (int q = 0; q < nv; ++q) se += expf(va[q] - rmax);
    ssum[tid] = se;
    __syncthreads();
    for (int s = 128; s > 0; s >>= 1) {
        if (tid < s) ssum[tid] += ssum[tid + s];
        __syncthreads();
    }
    if (tid == 0) {
        g_rowmax[row] = rmax;
        g_sumexp[row] = ssum[0];
        g_rowarg[row] = sidx[0];
        g_y[row] = sidx[0];
        g_ptrg[row] = 1.0f / ssum[0];
    }
}

__global__ void mark_kernel() {
    int i = blockIdx.x * blockDim.x + threadIdx.x;
    if (i < BROWS) {
        int c = g_y[i];
        g_allowed[c] = 0;
        atomicAdd(&g_count[c], 1);
    }
}

__global__ void scan_kernel() {
    if (threadIdx.x == 0 && blockIdx.x == 0) {
        int s = 0;
        for (int c = 0; c < NCLS; ++c) { g_start[c] = s; s += g_count[c]; }
        g_start[NCLS] = s;   // sentinel: == BROWS
    }
}

__global__ void scatter_kernel() {
    int i = blockIdx.x * blockDim.x + threadIdx.x;
    if (i < BROWS) {
        int c = g_y[i];
        int pos = g_start[c] + atomicAdd(&g_cursor[c], 1);
        g_member[pos]    = i;
        g_classOf[pos]   = c;
        g_slotOfRow[i]   = pos;
    }
}

__global__ void maskw_kernel() {
    int w = threadIdx.x;   // 32 threads
    unsigned int m = 0;
    for (int b = 0; b < 32; ++b) {
        int c = w * 32 + b;
        if (c < NCLS && g_allowed[c]) m |= (1u << b);
    }
    g_maskw[w] = m;
}

// masked top over z + fill initial topu buffer 0 (slot order)
__global__ void topz_kernel() {
    int row = blockIdx.x;
    int tid = threadIdx.x;
    float tmax = -1000.0f;
    for (int c = tid; c < NCLS; c += 256) {
        if (g_allowed[c]) {
            float v = g_z[(size_t)row * NCLS + c];
            if (v > tmax) tmax = v;
        }
    }
    __shared__ float st[256];
    st[tid] = tmax;
    __syncthreads();
    for (int s = 128; s > 0; s >>= 1) {
        if (tid < s) { float o = st[tid + s]; if (o > st[tid]) st[tid] = o; }
        __syncthreads();
    }
    if (tid == 0) {
        g_topz[row] = st[0];
        g_topu2[0][g_slotOfRow[row]] = st[0];
    }
}

// T[i][k], one block per row; z-row staged (coalesced); topz via g_topu2[0][k]
// (same stored float). Per-element formula unchanged -> bit-exact.
__global__ void __launch_bounds__(256)
computeT_kernel() {
    __shared__ float s_z[NCLS];
    const int i   = blockIdx.x;
    const int tid = threadIdx.x;
    for (int c = tid; c < NCLS; c += 256)
        s_z[c] = g_z[(size_t)i * NCLS + c];
    __syncthreads();
    const size_t base = (size_t)i << 11;
#pragma unroll
    for (int q = 0; q < 8; ++q) {
        int k = tid + q * 256;
        int c = g_classOf[k];
        float tz = g_topu2[0][k];
        float lorg = s_z[c] - tz;
        float latr = (floorf(lorg / TAUc) + 0.5f) * TAUc;
        float arg  = PI_F * (1.0f - 2.0f * (lorg - latr) / TAUc);
        g_T[base + k] = lorg - TAUc * sinf(arg);
    }
}

__global__ void init_u_kernel(float* __restrict__ u) {
    int idx = blockIdx.x * blockDim.x + threadIdx.x;
    u[idx]    = g_z[idx];
    g_mv[idx] = make_float2(0.f, 0.f);
}

// ---------------- global reduce: 512 thr, float4, shuffle trees (exact ops) ----
__global__ void __launch_bounds__(512)
reduce_kernel() {
    __shared__ float swv[16];
    __shared__ int   swi[16];
    __shared__ float sws[16];
    __shared__ float s_pmax;
    __shared__ int   s_istar;
    const int tid  = threadIdx.x;
    const int lane = tid & 31;
    const int warp = tid >> 5;

    // argmin of sumexp (exact: lowest-index tie, ascending processing)
    float4 w = *reinterpret_cast<const float4*>(&g_sumexp[tid * 4]);
    float best = w.x; int bi = tid * 4;
    if (w.y < best) { best = w.y; bi = tid * 4 + 1; }
    if (w.z < best) { best = w.z; bi = tid * 4 + 2; }
    if (w.w < best) { best = w.w; bi = tid * 4 + 3; }
#pragma unroll
    for (int off = 16; off > 0; off >>= 1) {
        float ov = __shfl_down_sync(0xffffffffu, best, off);
        int   oi = __shfl_down_sync(0xffffffffu, bi, off);
        if (ov < best || (ov == best && oi < bi)) { best = ov; bi = oi; }
    }
    if (lane == 0) { swv[warp] = best; swi[warp] = bi; }
    __syncthreads();
    if (warp == 0) {
        float v = (lane < 16) ? swv[lane] : 3.402823466e38f;
        int   ix = (lane < 16) ? swi[lane] : (1 << 30);
#pragma unroll
        for (int off = 8; off > 0; off >>= 1) {
            float ov = __shfl_down_sync(0xffffffffu, v, off);
            int   oi = __shfl_down_sync(0xffffffffu, ix, off);
            if (ov < v || (ov == v && oi < ix)) { v = ov; ix = oi; }
        }
        if (lane == 0) { s_istar = ix; s_pmax = 1.0f / v; }
    }
    __syncthreads();
    const float pmax = s_pmax;

    // sign sum (exact: +-1 integers in fp32, any association)
    float4 pt = *reinterpret_cast<const float4*>(&g_ptrg[tid * 4]);
    float s1 = 0.f, d;
    d = pmax - pt.x; s1 += (d > 0.f) ? 1.f : ((d < 0.f) ? -1.f : 0.f);
    d = pmax - pt.y; s1 += (d > 0.f) ? 1.f : ((d < 0.f) ? -1.f : 0.f);
    d = pmax - pt.z; s1 += (d > 0.f) ? 1.f : ((d < 0.f) ? -1.f : 0.f);
    d = pmax - pt.w; s1 += (d > 0.f) ? 1.f : ((d < 0.f) ? -1.f : 0.f);
#pragma unroll
    for (int off = 16; off > 0; off >>= 1)
        s1 += __shfl_down_sync(0xffffffffu, s1, off);
    if (lane == 0) sws[warp] = s1;
    __syncthreads();
    if (warp == 0) {
        float s = (lane < 16) ? sws[lane] : 0.f;
#pragma unroll
        for (int off = 8; off > 0; off >>= 1)
            s += __shfl_down_sync(0xffffffffu, s, off);
        if (lane == 0) {
            int istar = s_istar;
            g_istar      = istar;
            g_cstar      = g_rowarg[istar];
            g_rmaxstar   = g_rowmax[istar];
            g_sumexpstar = g_sumexp[istar];
            g_coef       = BETAc * 2048.0f * s * pmax;
        }
    }
}

// ---------------- fused per-step kernel ----------------
// Thread handles 4 CONSECUTIVE columns (c = 4*tid..4*tid+3) -> u/mv RMW as
// float4 (fewer L2 requests). BIT-EXACT: per-column Adam/gradient math is
// column-independent (same values whichever thread computes them);
// max/argmax/topu are exact order-free ops; the rounding-sensitive sumexp is
// computed from new-u staged in smem, read in R1's exact column order
// (c = tid + 256q ascending) with R1's exact tree pairing.
__global__ void __launch_bounds__(256, 6)
fused_kernel(float* __restrict__ u, int parity, float bc1, float bc2) {
    __shared__ float2 s_pair[BROWS];     // {topu[k], T[k]}
    __shared__ __align__(16) float s_u[NCLS];
    __shared__ float smax[256];
    __shared__ int   sidx[256];
    __shared__ float stp[256];
    __shared__ float ssum[256];
    __shared__ unsigned int s_mask[32];

    const int i    = blockIdx.x;
    const int tid  = threadIdx.x;
    const int lane = tid & 31;
    const int warp = tid >> 5;
    const float* __restrict__ topuIn = g_topu2[parity];
    float* __restrict__ topuOut      = g_topu2[parity ^ 1];

    {   // stage paired {topu, T} (float4 loads, float2 interleaved stores)
        const float4* T4  = reinterpret_cast<const float4*>(g_T + ((size_t)i << 11));
        const float4* tu4 = reinterpret_cast<const float4*>(topuIn);
        float4 t0 = T4[tid];
        float4 u0 = tu4[tid];
        float4 t1 = T4[tid + 256];
        float4 u1 = tu4[tid + 256];
        int k0 = tid * 4;
        s_pair[k0 + 0] = make_float2(u0.x, t0.x);
        s_pair[k0 + 1] = make_float2(u0.y, t0.y);
        s_pair[k0 + 2] = make_float2(u0.z, t0.z);
        s_pair[k0 + 3] = make_float2(u0.w, t0.w);
        int k1 = (tid + 256) * 4;
        s_pair[k1 + 0] = make_float2(u1.x, t1.x);
        s_pair[k1 + 1] = make_float2(u1.y, t1.y);
        s_pair[k1 + 2] = make_float2(u1.z, t1.z);
        s_pair[k1 + 3] = make_float2(u1.w, t1.w);
        if (tid < 32) s_mask[tid] = g_maskw[tid];
    }
    const int   istar      = g_istar;      // written by previous reduce launch
    const int   cstar      = g_cstar;
    const float rmaxstar   = g_rmaxstar;
    const float sumexpstar = g_sumexpstar;
    const float coef       = g_coef;

    // hoisted vector loads: 4 consecutive columns per thread
    const int c0 = tid * 4;
    const bool active = (c0 < NCLS);       // tid < 250
    float4 uv4 = make_float4(0.f, 0.f, 0.f, 0.f);
    float4 m01 = uv4, m23 = uv4;
    int st5[5] = {0, 0, 0, 0, 0};
    if (active) {
        const int idx0 = i * NCLS + c0;
        uv4 = *reinterpret_cast<const float4*>(&u[idx0]);
        m01 = *reinterpret_cast<const float4*>(&g_mv[idx0]);      // mv[c0], mv[c0+1]
        m23 = *reinterpret_cast<const float4*>(&g_mv[idx0 + 2]);  // mv[c0+2], mv[c0+3]
        int4 s4 = *reinterpret_cast<const int4*>(&g_start[c0]);
        st5[0] = s4.x; st5[1] = s4.y; st5[2] = s4.z; st5[3] = s4.w;
        st5[4] = g_start[c0 + 4];
    }
    __syncthreads();

    // ---- gradient + Adam + u update (per-column independent -> bit-exact) ----
    float uvA[4] = {uv4.x, uv4.y, uv4.z, uv4.w};
    float mA[4]  = {m01.x, m01.z, m23.x, m23.z};
    float vA[4]  = {m01.y, m01.w, m23.y, m23.w};
    float nu4[4];
    float vmax = -3.402823466e38f;
    int   vidx = NCLS;
    float tmax = -1000.0f;
    if (active) {
#pragma unroll
        for (int j = 0; j < 4; ++j) {
            const int c = c0 + j;
            float uv = uvA[j];
            float g = 0.f;
            for (int k = st5[j]; k < st5[j + 1]; ++k) {
                float2 p = s_pair[k];
                float d = uv - p.x - p.y;
                g += (d > 0.f) ? 1.f : ((d < 0.f) ? -1.f : 0.f);
            }
            if (i == istar) {
                float p = expf(uv - rmaxstar) / sumexpstar;
                float ind = (c == cstar) ? 1.f : 0.f;
                g += coef * (ind - p);
            }
            float mv = B1c * mA[j] + (1.0f - B1c) * g;
            float vv = B2c * vA[j] + (1.0f - B2c) * g * g;
            mA[j] = mv; vA[j] = vv;
            float mhat = mv / bc1;
            float vhat = vv / bc2;
            float nu = uv - LRc * mhat / (sqrtf(vhat) + EPSc);
            nu4[j] = nu;
            if (nu > vmax) { vmax = nu; vidx = c; }
            if ((s_mask[c >> 5] >> (c & 31)) & 1u) { if (nu > tmax) tmax = nu; }
        }
        const int idx0 = i * NCLS + c0;
        *reinterpret_cast<float4*>(&u[idx0]) =
            make_float4(nu4[0], nu4[1], nu4[2], nu4[3]);
        *reinterpret_cast<float4*>(&g_mv[idx0]) =
            make_float4(mA[0], vA[0], mA[1], vA[1]);
        *reinterpret_cast<float4*>(&g_mv[idx0 + 2]) =
            make_float4(mA[2], vA[2], mA[3], vA[3]);
        *reinterpret_cast<float4*>(&s_u[c0]) =
            make_float4(nu4[0], nu4[1], nu4[2], nu4[3]);
    }

    // ---- max/argmax/topu: EXACT ops -> warp-shuffle-first (order-free) ----
#pragma unroll
    for (int off = 16; off > 0; off >>= 1) {
        float ov = __shfl_down_sync(0xffffffffu, vmax, off);
        int   oi = __shfl_down_sync(0xffffffffu, vidx, off);
        float ot = __shfl_down_sync(0xffffffffu, tmax, off);
        if (ov > vmax || (ov == vmax && oi < vidx)) { vmax = ov; vidx = oi; }
        if (ot > tmax) tmax = ot;
    }
    if (lane == 0) { smax[warp] = vmax; sidx[warp] = vidx; stp[warp] = tmax; }
    __syncthreads();
    if (tid < 8) {
        float mv_ = smax[tid]; int mi_ = sidx[tid]; float tp_ = stp[tid];
        __syncwarp(0x000000ffu);
#pragma unroll
        for (int off = 4; off > 0; off >>= 1) {
            float ov = __shfl_down_sync(0x000000ffu, mv_, off);
            int   oi = __shfl_down_sync(0x000000ffu, mi_, off);
            float ot = __shfl_down_sync(0x000000ffu, tp_, off);
            if (ov > mv_ || (ov == mv_ && oi < mi_)) { mv_ = ov; mi_ = oi; }
            if (ot > tp_) tp_ = ot;
        }
        if (tid == 0) { smax[0] = mv_; sidx[0] = mi_; stp[0] = tp_; }
    }
    __syncthreads();
    const float rmax  = smax[0];
    const int   argr  = sidx[0];
    const float tmaxr = stp[0];

    // ---- sumexp: R1's exact column order + tree pairing (rounding-sensitive) ----
    float se = 0.f;
    for (int c = tid; c < NCLS; c += 256) se += expf(s_u[c] - rmax);
    ssum[tid] = se;
    __syncthreads();
#pragma unroll
    for (int s = 128; s >= 32; s >>= 1) {
        if (tid < s) ssum[tid] += ssum[tid + s];
        __syncthreads();
    }
    if (tid < 32) {
        float sum_ = ssum[tid];
        __syncwarp(0xffffffffu);
#pragma unroll
        for (int off = 16; off > 0; off >>= 1)
            sum_ += __shfl_down_sync(0xffffffffu, sum_, off);
        if (tid == 0) {
            g_rowmax[i] = rmax;
            g_sumexp[i] = sum_;
            g_rowarg[i] = argr;
            topuOut[g_slotOfRow[i]] = tmaxr;
        }
    }
}

// ---------------- launch ----------------
extern "C" void kernel_launch(void* const* d_in, const int* in_sizes, int n_in,
                              void* d_out, int out_size) {
    const float* x = nullptr; const float* W = nullptr; const float* b = nullptr;
    for (int i = 0; i < n_in; ++i) {
        if (in_sizes[i] == BROWS * KDIM)      x = (const float*)d_in[i];
        else if (in_sizes[i] == KDIM * NCLS)  W = (const float*)d_in[i];
        else if (in_sizes[i] == NCLS)         b = (const float*)d_in[i];
    }
    float* u = (float*)d_out;

    dim3 gemm_grid((NCLS + 63) / 64, BROWS / 128);
    gemm_kernel<<<gemm_grid, 256>>>(x, W, b);

    init_class_kernel<<<4, 256>>>();
    statsz_kernel<<<BROWS, 256>>>();
    mark_kernel<<<8, 256>>>();
    scan_kernel<<<1, 1>>>();
    scatter_kernel<<<8, 256>>>();
    maskw_kernel<<<1, 32>>>();
    topz_kernel<<<BROWS, 256>>>();
    computeT_kernel<<<BROWS, 256>>>();
    init_u_kernel<<<(BROWS * NCLS) / 256, 256>>>(u);
    reduce_kernel<<<1, 512>>>();

    for (int t = 1; t <= NSTEPS; ++t) {
        float bc1 = (float)(1.0 - pow((double)B1c, (double)t));
        float bc2 = (float)(1.0 - pow((double)B2c, (double)t));
        fused_kernel<<<BROWS, 256>>>(u, (t - 1) & 1, bc1, bc2);
        reduce_kernel<<<1, 512>>>();
    }
}